// round 2
// baseline (speedup 1.0000x reference)
#include <cuda_runtime.h>
#include <cuda_bf16.h>
#include <cstdint>

// ---------------------------------------------------------------------------
// Problem: EstimateAdj
//   h    = relu(features @ W1 + b1)          [N,128] -> [N,64]
//   reps = h @ W2 + b2                        [N,64]
//   total_edge_index = concat(ei, pei, axis=1)
//   pw[e] = relu(dot(reps[ei0[e]], reps[ei1[e]]))  for e < E_ORIG only
//
// NOTE: edge_index / pred_edge_index arrive as int32 (harness downcasts int64).
//
// Output (float32, flattened concat):
//   [0, N*64)                     reps
//   [N*64, N*64+Eo)               predictor_weights
//   [.., +2*(Eo+Ec))              total_edge_index as float (row0: ei0++pei0, row1: ei1++pei1)
//   [.., +2*Eo)                   edge_index as float (ei0 ++ ei1)
// ---------------------------------------------------------------------------

#define MLP_THREADS 256
#define NPB 64            // nodes per block
#define HS_STRIDE 68      // padded stride for h tile (floats)

// Fused 2-layer MLP. Each block: 64 nodes. Each thread: 4 nodes x 4 cols.
// Shared layout: [W1s: 8192 floats][W2s: 4096 floats], h tile reuses W1s space
// after GEMM1 (W1 dead by then). Total 49152 B = default dynamic smem limit.
__global__ void __launch_bounds__(MLP_THREADS)
mlp_kernel(const float* __restrict__ feat,
           const float* __restrict__ W1, const float* __restrict__ b1,
           const float* __restrict__ W2, const float* __restrict__ b2,
           float* __restrict__ reps, int N)
{
    extern __shared__ float sh[];
    float* W1s = sh;                 // 128*64 = 8192 floats (32 KB)
    float* W2s = sh + 8192;          // 64*64  = 4096 floats (16 KB)
    float* hs  = sh;                 // reuses W1s region: 64*68 = 4352 floats

    const int tx = threadIdx.x;

    // Cooperative load of W1, W2 into shared (float4, coalesced)
    {
        const float4* w1g = (const float4*)W1;
        float4* w1sv = (float4*)W1s;
        #pragma unroll
        for (int i = 0; i < 8; i++) w1sv[tx + 256 * i] = w1g[tx + 256 * i];
        const float4* w2g = (const float4*)W2;
        float4* w2sv = (float4*)W2s;
        #pragma unroll
        for (int i = 0; i < 4; i++) w2sv[tx + 256 * i] = w2g[tx + 256 * i];
    }
    __syncthreads();

    const int c = tx & 15;   // column group: cols [c*4, c*4+4)
    const int r = tx >> 4;   // node group:   nodes [r*4, r*4+4) within block
    const int nbase = blockIdx.x * NPB + r * 4;

    float acc[4][4];
    #pragma unroll
    for (int i = 0; i < 4; i++)
        #pragma unroll
        for (int j = 0; j < 4; j++) acc[i][j] = 0.f;

    // ---- GEMM1: h = X @ W1, K = 128 ----
    #pragma unroll 4
    for (int k4 = 0; k4 < 32; k4++) {
        float4 f[4];
        #pragma unroll
        for (int i = 0; i < 4; i++) {
            int n = nbase + i;
            f[i] = (n < N) ? *(const float4*)(feat + (size_t)n * 128 + k4 * 4)
                           : make_float4(0.f, 0.f, 0.f, 0.f);
        }
        #pragma unroll
        for (int kk = 0; kk < 4; kk++) {
            float4 w = *(const float4*)(W1s + (k4 * 4 + kk) * 64 + c * 4);
            #pragma unroll
            for (int i = 0; i < 4; i++) {
                float fv = (kk == 0) ? f[i].x : (kk == 1) ? f[i].y
                         : (kk == 2) ? f[i].z : f[i].w;
                acc[i][0] += fv * w.x;
                acc[i][1] += fv * w.y;
                acc[i][2] += fv * w.z;
                acc[i][3] += fv * w.w;
            }
        }
    }

    // All threads done reading W1s before we overwrite it with the h tile.
    __syncthreads();

    // bias + relu -> h tile in shared (W1s region, now dead)
    {
        float4 bb = *(const float4*)(b1 + c * 4);
        #pragma unroll
        for (int i = 0; i < 4; i++) {
            float4 hv;
            hv.x = fmaxf(acc[i][0] + bb.x, 0.f);
            hv.y = fmaxf(acc[i][1] + bb.y, 0.f);
            hv.z = fmaxf(acc[i][2] + bb.z, 0.f);
            hv.w = fmaxf(acc[i][3] + bb.w, 0.f);
            *(float4*)(hs + (r * 4 + i) * HS_STRIDE + c * 4) = hv;
        }
    }
    __syncthreads();

    // ---- GEMM2: reps = h @ W2, K = 64 ----
    #pragma unroll
    for (int i = 0; i < 4; i++)
        #pragma unroll
        for (int j = 0; j < 4; j++) acc[i][j] = 0.f;

    #pragma unroll 4
    for (int k4 = 0; k4 < 16; k4++) {
        float4 h4[4];
        #pragma unroll
        for (int i = 0; i < 4; i++)
            h4[i] = *(const float4*)(hs + (r * 4 + i) * HS_STRIDE + k4 * 4);
        #pragma unroll
        for (int kk = 0; kk < 4; kk++) {
            float4 w = *(const float4*)(W2s + (k4 * 4 + kk) * 64 + c * 4);
            #pragma unroll
            for (int i = 0; i < 4; i++) {
                float hv = (kk == 0) ? h4[i].x : (kk == 1) ? h4[i].y
                         : (kk == 2) ? h4[i].z : h4[i].w;
                acc[i][0] += hv * w.x;
                acc[i][1] += hv * w.y;
                acc[i][2] += hv * w.z;
                acc[i][3] += hv * w.w;
            }
        }
    }

    {
        float4 bb = *(const float4*)(b2 + c * 4);
        #pragma unroll
        for (int i = 0; i < 4; i++) {
            int n = nbase + i;
            if (n < N) {
                float4 o;
                o.x = acc[i][0] + bb.x;
                o.y = acc[i][1] + bb.y;
                o.z = acc[i][2] + bb.z;
                o.w = acc[i][3] + bb.w;
                *(float4*)(reps + (size_t)n * 64 + c * 4) = o;
            }
        }
    }
}

// Edge dot-products: 8 threads per edge, 2x float4 each, shfl reduction.
__global__ void __launch_bounds__(256)
edge_dot_kernel(const float* __restrict__ reps,
                const int* __restrict__ ei,  // [2, Eo] row-major, int32
                long long Eo, float* __restrict__ pw, int N)
{
    long long t = (long long)blockIdx.x * blockDim.x + threadIdx.x;
    long long e = t >> 3;
    int l = (int)(t & 7);
    if (e >= Eo) return;

    int i0 = ei[e];
    int i1 = ei[e + Eo];
    // indices are in [0, N) by construction; clamp defensively (branch-free)
    i0 = min(max(i0, 0), N - 1);
    i1 = min(max(i1, 0), N - 1);

    const float4* p0 = (const float4*)(reps + (size_t)i0 * 64 + l * 8);
    const float4* p1 = (const float4*)(reps + (size_t)i1 * 64 + l * 8);
    float4 a0 = p0[0], a1 = p0[1];
    float4 b0 = p1[0], b1 = p1[1];

    float acc = a0.x * b0.x + a0.y * b0.y + a0.z * b0.z + a0.w * b0.w
              + a1.x * b1.x + a1.y * b1.y + a1.z * b1.z + a1.w * b1.w;

    acc += __shfl_xor_sync(0xffffffffu, acc, 4);
    acc += __shfl_xor_sync(0xffffffffu, acc, 2);
    acc += __shfl_xor_sync(0xffffffffu, acc, 1);

    if (l == 0) pw[e] = fmaxf(acc, 0.f);
}

// Copy / cast indices into the output layout.
__global__ void __launch_bounds__(256)
copy_idx_kernel(const int* __restrict__ ei,
                const int* __restrict__ pei,
                long long Eo, long long Ec,
                float* __restrict__ out_tei,  // 2*(Eo+Ec) floats
                float* __restrict__ out_ei)   // 2*Eo floats
{
    long long i = (long long)blockIdx.x * blockDim.x + threadIdx.x;
    long long Et = Eo + Ec;
    if (i < Eo) {
        float v0 = (float)ei[i];
        float v1 = (float)ei[i + Eo];
        out_tei[i]      = v0;
        out_tei[Et + i] = v1;
        out_ei[i]       = v0;
        out_ei[Eo + i]  = v1;
    }
    if (i < Ec) {
        out_tei[Eo + i]      = (float)pei[i];
        out_tei[Et + Eo + i] = (float)pei[i + Ec];
    }
}

extern "C" void kernel_launch(void* const* d_in, const int* in_sizes, int n_in,
                              void* d_out, int out_size)
{
    const float* feat = (const float*)d_in[0];
    const int*   ei   = (const int*)d_in[1];
    const int*   pei  = (const int*)d_in[2];
    const float* W1   = (const float*)d_in[3];
    const float* b1   = (const float*)d_in[4];
    const float* W2   = (const float*)d_in[5];
    const float* b2   = (const float*)d_in[6];
    float* out = (float*)d_out;

    const int N        = in_sizes[0] / 128;
    const long long Eo = in_sizes[1] / 2;
    const long long Ec = in_sizes[2] / 2;

    float* reps    = out;                               // N*64
    float* pw      = out + (size_t)N * 64;              // Eo
    float* out_tei = pw + Eo;                           // 2*(Eo+Ec)
    float* out_ei  = out_tei + 2 * (Eo + Ec);           // 2*Eo

    // Fused MLP. Dynamic smem = 49152 B (default limit, no attribute call).
    const int shmem = (8192 + 4096) * (int)sizeof(float);
    int mlp_blocks = (N + NPB - 1) / NPB;
    mlp_kernel<<<mlp_blocks, MLP_THREADS, shmem>>>(feat, W1, b1, W2, b2, reps, N);

    // Edge dot products (reads reps from d_out, L2-resident)
    long long edge_threads = Eo * 8;
    int edge_blocks = (int)((edge_threads + 255) / 256);
    edge_dot_kernel<<<edge_blocks, 256>>>(reps, ei, Eo, pw, N);

    // Index copies (independent of the above)
    int copy_blocks = (int)((Eo + 255) / 256);
    copy_idx_kernel<<<copy_blocks, 256>>>(ei, pei, Eo, Ec, out_tei, out_ei);
}

// round 3
// speedup vs baseline: 1.2950x; 1.2950x over previous
#include <cuda_runtime.h>
#include <cuda_fp16.h>
#include <cuda_bf16.h>
#include <cstdint>

// ---------------------------------------------------------------------------
// EstimateAdj:
//   h    = relu(features @ W1 + b1)   [N,128]->[N,64]
//   reps = h @ W2 + b2                [N,64]
//   pw[e] = relu(dot(reps[ei0[e]], reps[ei1[e]]))  e < Eo
// Output (float32 concat): reps | pw | total_edge_index | edge_index
//
// R3 changes vs R2 (143.4us):
//  - fp16 shadow copy of reps -> edge gather L2 traffic halved (819->410MB)
//  - index-copy blocks appended to MLP grid (DRAM copy hides under FMA-bound MLP)
// ---------------------------------------------------------------------------

#define MLP_THREADS 256
#define NPB 64            // nodes per MLP block
#define HS_STRIDE 68      // padded h-tile stride (floats)
#define N_MAX 100000

// fp16 shadow of reps, stored as half2 (32 half2 per node = 64 halfs = 128B/row)
__device__ __half2 g_reps_h[N_MAX * 32];

// Fused 2-layer MLP + (role-split) index copy.
// Blocks [0, mlp_blocks): MLP on 64 nodes each.
// Blocks [mlp_blocks, ..): convert/copy edge indices (independent of MLP,
// DRAM-bound -> overlaps with the FMA-bound MLP blocks in the same launch).
__global__ void __launch_bounds__(MLP_THREADS)
mlp_plus_copy_kernel(const float* __restrict__ feat,
                     const float* __restrict__ W1, const float* __restrict__ b1,
                     const float* __restrict__ W2, const float* __restrict__ b2,
                     float* __restrict__ reps, int N, int mlp_blocks,
                     const int* __restrict__ ei, const int* __restrict__ pei,
                     long long Eo, long long Ec,
                     float* __restrict__ out_tei, float* __restrict__ out_ei)
{
    const int tx = threadIdx.x;

    if (blockIdx.x >= mlp_blocks) {
        // ---------------- index copy role (vectorized x4) ----------------
        long long i = ((long long)(blockIdx.x - mlp_blocks) * MLP_THREADS + tx) * 4;
        long long Et = Eo + Ec;
        if (i < Eo) {
            int4 v0 = *(const int4*)(ei + i);
            int4 v1 = *(const int4*)(ei + Eo + i);
            float4 f0 = make_float4((float)v0.x, (float)v0.y, (float)v0.z, (float)v0.w);
            float4 f1 = make_float4((float)v1.x, (float)v1.y, (float)v1.z, (float)v1.w);
            *(float4*)(out_tei + i)      = f0;
            *(float4*)(out_tei + Et + i) = f1;
            *(float4*)(out_ei + i)       = f0;
            *(float4*)(out_ei + Eo + i)  = f1;
        }
        if (i < Ec) {
            int4 v0 = *(const int4*)(pei + i);
            int4 v1 = *(const int4*)(pei + Ec + i);
            float4 f0 = make_float4((float)v0.x, (float)v0.y, (float)v0.z, (float)v0.w);
            float4 f1 = make_float4((float)v1.x, (float)v1.y, (float)v1.z, (float)v1.w);
            *(float4*)(out_tei + Eo + i)      = f0;
            *(float4*)(out_tei + Et + Eo + i) = f1;
        }
        return;
    }

    // ---------------- MLP role ----------------
    extern __shared__ float sh[];
    float* W1s = sh;                 // 128*64 floats (32 KB)
    float* W2s = sh + 8192;          // 64*64 floats (16 KB)
    float* hs  = sh;                 // h tile reuses W1s region after GEMM1

    {
        const float4* w1g = (const float4*)W1;
        float4* w1sv = (float4*)W1s;
        #pragma unroll
        for (int i = 0; i < 8; i++) w1sv[tx + 256 * i] = w1g[tx + 256 * i];
        const float4* w2g = (const float4*)W2;
        float4* w2sv = (float4*)W2s;
        #pragma unroll
        for (int i = 0; i < 4; i++) w2sv[tx + 256 * i] = w2g[tx + 256 * i];
    }
    __syncthreads();

    const int c = tx & 15;   // cols [c*4, c*4+4)
    const int r = tx >> 4;   // nodes [r*4, r*4+4) within block
    const int nbase = blockIdx.x * NPB + r * 4;

    float acc[4][4];
    #pragma unroll
    for (int i = 0; i < 4; i++)
        #pragma unroll
        for (int j = 0; j < 4; j++) acc[i][j] = 0.f;

    // ---- GEMM1: h = X @ W1, K=128 ----
    #pragma unroll 4
    for (int k4 = 0; k4 < 32; k4++) {
        float4 f[4];
        #pragma unroll
        for (int i = 0; i < 4; i++) {
            int n = nbase + i;
            f[i] = (n < N) ? *(const float4*)(feat + (size_t)n * 128 + k4 * 4)
                           : make_float4(0.f, 0.f, 0.f, 0.f);
        }
        #pragma unroll
        for (int kk = 0; kk < 4; kk++) {
            float4 w = *(const float4*)(W1s + (k4 * 4 + kk) * 64 + c * 4);
            #pragma unroll
            for (int i = 0; i < 4; i++) {
                float fv = (kk == 0) ? f[i].x : (kk == 1) ? f[i].y
                         : (kk == 2) ? f[i].z : f[i].w;
                acc[i][0] += fv * w.x;
                acc[i][1] += fv * w.y;
                acc[i][2] += fv * w.z;
                acc[i][3] += fv * w.w;
            }
        }
    }

    __syncthreads();  // all reads of W1s done before h overwrites it

    {
        float4 bb = *(const float4*)(b1 + c * 4);
        #pragma unroll
        for (int i = 0; i < 4; i++) {
            float4 hv;
            hv.x = fmaxf(acc[i][0] + bb.x, 0.f);
            hv.y = fmaxf(acc[i][1] + bb.y, 0.f);
            hv.z = fmaxf(acc[i][2] + bb.z, 0.f);
            hv.w = fmaxf(acc[i][3] + bb.w, 0.f);
            *(float4*)(hs + (r * 4 + i) * HS_STRIDE + c * 4) = hv;
        }
    }
    __syncthreads();

    // ---- GEMM2: reps = h @ W2, K=64 ----
    #pragma unroll
    for (int i = 0; i < 4; i++)
        #pragma unroll
        for (int j = 0; j < 4; j++) acc[i][j] = 0.f;

    #pragma unroll 4
    for (int k4 = 0; k4 < 16; k4++) {
        float4 h4[4];
        #pragma unroll
        for (int i = 0; i < 4; i++)
            h4[i] = *(const float4*)(hs + (r * 4 + i) * HS_STRIDE + k4 * 4);
        #pragma unroll
        for (int kk = 0; kk < 4; kk++) {
            float4 w = *(const float4*)(W2s + (k4 * 4 + kk) * 64 + c * 4);
            #pragma unroll
            for (int i = 0; i < 4; i++) {
                float hv = (kk == 0) ? h4[i].x : (kk == 1) ? h4[i].y
                         : (kk == 2) ? h4[i].z : h4[i].w;
                acc[i][0] += hv * w.x;
                acc[i][1] += hv * w.y;
                acc[i][2] += hv * w.z;
                acc[i][3] += hv * w.w;
            }
        }
    }

    {
        float4 bb = *(const float4*)(b2 + c * 4);
        #pragma unroll
        for (int i = 0; i < 4; i++) {
            int n = nbase + i;
            if (n < N) {
                float4 o;
                o.x = acc[i][0] + bb.x;
                o.y = acc[i][1] + bb.y;
                o.z = acc[i][2] + bb.z;
                o.w = acc[i][3] + bb.w;
                *(float4*)(reps + (size_t)n * 64 + c * 4) = o;
                // fp16 shadow for the edge gather (half2 pairs)
                __half2 h0 = __floats2half2_rn(o.x, o.y);
                __half2 h1 = __floats2half2_rn(o.z, o.w);
                g_reps_h[(size_t)n * 32 + c * 2]     = h0;
                g_reps_h[(size_t)n * 32 + c * 2 + 1] = h1;
            }
        }
    }
}

__device__ __forceinline__ float dot8h(uint4 a, uint4 b) {
    const __half2* pa = (const __half2*)&a;
    const __half2* pb = (const __half2*)&b;
    float acc = 0.f;
    #pragma unroll
    for (int j = 0; j < 4; j++) {
        float2 x = __half22float2(pa[j]);
        float2 y = __half22float2(pb[j]);
        acc = fmaf(x.x, y.x, acc);
        acc = fmaf(x.y, y.y, acc);
    }
    return acc;
}

// Edge dot products on the fp16 shadow: 4 threads/edge, 32B per thread per row,
// fp32 accumulation, shfl reduce.
__global__ void __launch_bounds__(256)
edge_dot_kernel(const int* __restrict__ ei, long long Eo,
                float* __restrict__ pw, int N)
{
    long long t = (long long)blockIdx.x * blockDim.x + threadIdx.x;
    long long e = t >> 2;
    int l = (int)(t & 3);
    if (e >= Eo) return;

    int i0 = ei[e];
    int i1 = ei[e + Eo];
    i0 = min(max(i0, 0), N - 1);   // defensive clamp, branch-free
    i1 = min(max(i1, 0), N - 1);

    const uint4* A = (const uint4*)(g_reps_h + (size_t)i0 * 32);  // 8 x uint4 per row
    const uint4* B = (const uint4*)(g_reps_h + (size_t)i1 * 32);

    uint4 a0 = A[l * 2], a1 = A[l * 2 + 1];
    uint4 b0 = B[l * 2], b1 = B[l * 2 + 1];

    float acc = dot8h(a0, b0) + dot8h(a1, b1);

    acc += __shfl_xor_sync(0xffffffffu, acc, 2);
    acc += __shfl_xor_sync(0xffffffffu, acc, 1);

    if (l == 0) pw[e] = fmaxf(acc, 0.f);
}

extern "C" void kernel_launch(void* const* d_in, const int* in_sizes, int n_in,
                              void* d_out, int out_size)
{
    const float* feat = (const float*)d_in[0];
    const int*   ei   = (const int*)d_in[1];
    const int*   pei  = (const int*)d_in[2];
    const float* W1   = (const float*)d_in[3];
    const float* b1   = (const float*)d_in[4];
    const float* W2   = (const float*)d_in[5];
    const float* b2   = (const float*)d_in[6];
    float* out = (float*)d_out;

    const int N        = in_sizes[0] / 128;
    const long long Eo = in_sizes[1] / 2;
    const long long Ec = in_sizes[2] / 2;

    float* reps    = out;
    float* pw      = out + (size_t)N * 64;
    float* out_tei = pw + Eo;
    float* out_ei  = out_tei + 2 * (Eo + Ec);

    const int shmem = (8192 + 4096) * (int)sizeof(float);  // 48 KB, default limit
    int mlp_blocks = (N + NPB - 1) / NPB;
    long long copy_items = (Eo > Ec ? Eo : Ec);
    int copy_blocks = (int)((copy_items + MLP_THREADS * 4 - 1) / (MLP_THREADS * 4));

    mlp_plus_copy_kernel<<<mlp_blocks + copy_blocks, MLP_THREADS, shmem>>>(
        feat, W1, b1, W2, b2, reps, N, mlp_blocks,
        ei, pei, Eo, Ec, out_tei, out_ei);

    long long edge_threads = Eo * 4;
    int edge_blocks = (int)((edge_threads + 255) / 256);
    edge_dot_kernel<<<edge_blocks, 256>>>(ei, Eo, pw, N);
}